// round 2
// baseline (speedup 1.0000x reference)
#include <cuda_runtime.h>
#include <cstdint>

#define N_NODES 100000
#define N_EDGES 1600000
#define N_GRAPHS 512
#define FDIM 128
#define SCAN_CHUNK 512
#define SCAN_BLOCKS ((N_NODES + SCAN_CHUNK - 1) / SCAN_CHUNK)   // 196

// ---------------- device scratch (allocation-free: __device__ globals) ------
__device__ float    g_h[(size_t)N_NODES * FDIM];
__device__ float    g_agg[(size_t)N_NODES * FDIM];
__device__ int      g_deg[N_NODES];
__device__ int      g_cursor[N_NODES];
__device__ float    g_dinv[N_NODES];
__device__ int      g_rowoff[N_NODES + 1];
__device__ unsigned long long g_edge[N_EDGES];   // (norm<<32)|src
__device__ int      g_part[SCAN_BLOCKS];
__device__ float    g_sums[N_GRAPHS * FDIM];
__device__ unsigned g_maxenc[N_GRAPHS * FDIM];
__device__ int      g_cnt[N_GRAPHS];

// ---------------- helpers ---------------------------------------------------
__device__ __forceinline__ unsigned enc_max(float f) {
    unsigned u = __float_as_uint(f);
    return (u & 0x80000000u) ? ~u : (u | 0x80000000u);
}
__device__ __forceinline__ float dec_max(unsigned e) {
    unsigned bits = (e & 0x80000000u) ? (e ^ 0x80000000u) : ~e;
    return __uint_as_float(bits);
}
__device__ __forceinline__ unsigned long long pk2(float v) {
    unsigned long long r;
    asm("mov.b64 %0,{%1,%1};" : "=l"(r) : "f"(v));
    return r;
}
__device__ __forceinline__ unsigned long long ffma2(unsigned long long a,
                                                    unsigned long long b,
                                                    unsigned long long c) {
    unsigned long long d;
    asm("fma.rn.f32x2 %0,%1,%2,%3;" : "=l"(d) : "l"(a), "l"(b), "l"(c));
    return d;
}
__device__ __forceinline__ void unpk2(unsigned long long v, float& lo, float& hi) {
    asm("mov.b64 {%0,%1},%2;" : "=f"(lo), "=f"(hi) : "l"(v));
}

// ---------------- preprocessing ---------------------------------------------
__global__ void zero_kernel() {
    int i = blockIdx.x * blockDim.x + threadIdx.x;
    if (i < N_GRAPHS * FDIM) { g_sums[i] = 0.0f; g_maxenc[i] = 0u; }
    if (i < N_GRAPHS) g_cnt[i] = 0;
    if (i < N_NODES) g_deg[i] = 0;
}

__global__ void hist_kernel(const int* __restrict__ dst) {
    int stride = gridDim.x * blockDim.x;
    for (int e = blockIdx.x * blockDim.x + threadIdx.x; e < N_EDGES; e += stride)
        atomicAdd(&g_deg[dst[e]], 1);
}

// phase 1: per-block partial sums (256 thr, 512 elems/block)
__global__ void scan_part() {
    int b = blockIdx.x, t = threadIdx.x;
    int base = b * SCAN_CHUNK;
    int s = 0;
    for (int i = t; i < SCAN_CHUNK; i += 256) {
        int idx = base + i;
        if (idx < N_NODES) s += g_deg[idx];
    }
    __shared__ int sh[8];
#pragma unroll
    for (int o = 16; o; o >>= 1) s += __shfl_down_sync(~0u, s, o);
    if ((t & 31) == 0) sh[t >> 5] = s;
    __syncthreads();
    if (t < 8) {
        int v = sh[t];
#pragma unroll
        for (int o = 4; o; o >>= 1) v += __shfl_down_sync(0xffu, v, o);
        if (t == 0) g_part[b] = v;
    }
}

// phase 2: 1-block exclusive scan of 196 partials
__global__ void scan_mid() {
    __shared__ int sh[256];
    int t = threadIdx.x;
    int v = (t < SCAN_BLOCKS) ? g_part[t] : 0;
    sh[t] = v;
    __syncthreads();
    for (int o = 1; o < 256; o <<= 1) {
        int u = (t >= o) ? sh[t - o] : 0;
        __syncthreads();
        sh[t] += u;
        __syncthreads();
    }
    if (t < SCAN_BLOCKS) g_part[t] = sh[t] - v;   // exclusive
    if (t == 0) g_rowoff[N_NODES] = N_EDGES;      // total degree is always E
}

// phase 3: per-block rescan + dinv + cursor reset (2 elems/thread)
__global__ void scan_final() {
    int b = blockIdx.x, t = threadIdx.x;
    int base = b * SCAN_CHUNK;
    int i0 = base + 2 * t, i1 = i0 + 1;
    int d0 = (i0 < N_NODES) ? g_deg[i0] : 0;
    int d1 = (i1 < N_NODES) ? g_deg[i1] : 0;
    int s = d0 + d1;
    __shared__ int sh[256];
    sh[t] = s;
    __syncthreads();
    for (int o = 1; o < 256; o <<= 1) {
        int u = (t >= o) ? sh[t - o] : 0;
        __syncthreads();
        sh[t] += u;
        __syncthreads();
    }
    int excl = sh[t] - s + g_part[b];
    if (i0 < N_NODES) {
        g_rowoff[i0] = excl;
        g_dinv[i0] = rsqrtf((float)d0 + 1.0f);
        g_cursor[i0] = 0;
    }
    if (i1 < N_NODES) {
        g_rowoff[i1] = excl + d0;
        g_dinv[i1] = rsqrtf((float)d1 + 1.0f);
        g_cursor[i1] = 0;
    }
}

__global__ void scatter_kernel(const int* __restrict__ src, const int* __restrict__ dst) {
    int stride = gridDim.x * blockDim.x;
    for (int e = blockIdx.x * blockDim.x + threadIdx.x; e < N_EDGES; e += stride) {
        int s = src[e], d = dst[e];
        int pos = g_rowoff[d] + atomicAdd(&g_cursor[d], 1);
        float norm = g_dinv[s] * g_dinv[d];
        g_edge[pos] = (unsigned long long)(unsigned)s |
                      ((unsigned long long)__float_as_uint(norm) << 32);
    }
}

// ---------------- dense GEMM via FFMA2: out[N,128] = act(A) @ W[128,128] ----
// 64-row tiles, 256 threads. As stored transposed (As[k*64+row]) so row-pairs
// are native f32x2 operands. W processed in 32-k blocks (16 KB tile).
template <bool RELU_IN>
__global__ void gemm128(const float* __restrict__ A, const float* __restrict__ W,
                        float* __restrict__ out) {
    __shared__ float As[64 * 128];   // 32 KB, transposed
    __shared__ float Ws[32 * 128];   // 16 KB
    int tid = threadIdx.x;
    int row0 = blockIdx.x * 64;

    // load A tile transposed
#pragma unroll
    for (int i = 0; i < 8; i++) {
        int idx = tid + i * 256;
        int r = idx & 63;
        int c4 = idx >> 6;
        int gr = row0 + r;
        if (gr >= N_NODES) gr = N_NODES - 1;
        float4 v = ((const float4*)(A + (size_t)gr * FDIM))[c4];
        if (RELU_IN) {
            v.x = fmaxf(v.x, 0.0f); v.y = fmaxf(v.y, 0.0f);
            v.z = fmaxf(v.z, 0.0f); v.w = fmaxf(v.w, 0.0f);
        }
        int cb = c4 * 4;
        As[(cb + 0) * 64 + r] = v.x;
        As[(cb + 1) * 64 + r] = v.y;
        As[(cb + 2) * 64 + r] = v.z;
        As[(cb + 3) * 64 + r] = v.w;
    }

    int warp = tid >> 5, lane = tid & 31;
    unsigned long long acc[4][4];
#pragma unroll
    for (int p = 0; p < 4; p++)
#pragma unroll
        for (int j = 0; j < 4; j++) acc[p][j] = 0ull;

    for (int kb = 0; kb < 4; kb++) {
        __syncthreads();
#pragma unroll
        for (int i = 0; i < 4; i++) {
            int idx = tid + i * 256;
            int k = idx >> 5, c4 = idx & 31;
            ((float4*)Ws)[k * 32 + c4] =
                ((const float4*)(W + (size_t)(kb * 32 + k) * FDIM))[c4];
        }
        __syncthreads();
#pragma unroll
        for (int k = 0; k < 32; k++) {
            float4 w = ((const float4*)Ws)[k * 32 + lane];
            unsigned long long wp0 = pk2(w.x), wp1 = pk2(w.y);
            unsigned long long wp2 = pk2(w.z), wp3 = pk2(w.w);
            int kk = kb * 32 + k;
            const unsigned long long* arow =
                (const unsigned long long*)&As[kk * 64 + warp * 8];
#pragma unroll
            for (int p = 0; p < 4; p++) {
                unsigned long long a2 = arow[p];
                acc[p][0] = ffma2(a2, wp0, acc[p][0]);
                acc[p][1] = ffma2(a2, wp1, acc[p][1]);
                acc[p][2] = ffma2(a2, wp2, acc[p][2]);
                acc[p][3] = ffma2(a2, wp3, acc[p][3]);
            }
        }
    }

    // store: rows row0 + warp*8 + 2p (+1), cols lane*4..lane*4+3
#pragma unroll
    for (int p = 0; p < 4; p++) {
        float4 vlo, vhi;
        unpk2(acc[p][0], vlo.x, vhi.x);
        unpk2(acc[p][1], vlo.y, vhi.y);
        unpk2(acc[p][2], vlo.z, vhi.z);
        unpk2(acc[p][3], vlo.w, vhi.w);
        int r = row0 + warp * 8 + 2 * p;
        if (r < N_NODES)     ((float4*)(out + (size_t)r * FDIM))[lane] = vlo;
        if (r + 1 < N_NODES) ((float4*)(out + (size_t)(r + 1) * FDIM))[lane] = vhi;
    }
}

// ---------------- aggregation: one warp per dst node (no atomics) -----------
__global__ void agg_kernel(const float* __restrict__ h, const float* __restrict__ bias,
                           float* __restrict__ out) {
    int warpid = (blockIdx.x * blockDim.x + threadIdx.x) >> 5;
    int lane = threadIdx.x & 31;
    if (warpid >= N_NODES) return;
    int node = warpid;

    float di = g_dinv[node];
    float sc = di * di;
    float4 b4 = ((const float4*)bias)[lane];
    float4 hv = ((const float4*)(h + (size_t)node * FDIM))[lane];
    float4 acc;
    acc.x = b4.x + hv.x * sc; acc.y = b4.y + hv.y * sc;
    acc.z = b4.z + hv.z * sc; acc.w = b4.w + hv.w * sc;

    int beg = g_rowoff[node], end = g_rowoff[node + 1];
    for (int i = beg; i < end; i++) {
        unsigned long long e = __ldg(&g_edge[i]);
        int s = (int)(unsigned)e;
        float w = __uint_as_float((unsigned)(e >> 32));
        float4 v = __ldg((const float4*)(h + (size_t)s * FDIM) + lane);
        acc.x += w * v.x; acc.y += w * v.y; acc.z += w * v.z; acc.w += w * v.w;
    }
    ((float4*)(out + (size_t)node * FDIM))[lane] = acc;
}

// ---------------- pooling: warp handles 32 consecutive nodes (sorted batch) -
__global__ void pool_kernel(const int* __restrict__ batch) {
    int warpid = (blockIdx.x * blockDim.x + threadIdx.x) >> 5;
    int lane = threadIdx.x & 31;
    int beg = warpid * 32;
    if (beg >= N_NODES) return;
    int end = min(beg + 32, N_NODES);

    int cur = batch[beg];
    float4 s = make_float4(0.f, 0.f, 0.f, 0.f);
    float4 m = make_float4(-INFINITY, -INFINITY, -INFINITY, -INFINITY);
    int cnt = 0;

    for (int node = beg; node < end; node++) {
        int b = batch[node];
        if (b != cur) {
            int base = cur * FDIM + lane * 4;
            atomicAdd(&g_sums[base + 0], s.x); atomicAdd(&g_sums[base + 1], s.y);
            atomicAdd(&g_sums[base + 2], s.z); atomicAdd(&g_sums[base + 3], s.w);
            atomicMax(&g_maxenc[base + 0], enc_max(m.x));
            atomicMax(&g_maxenc[base + 1], enc_max(m.y));
            atomicMax(&g_maxenc[base + 2], enc_max(m.z));
            atomicMax(&g_maxenc[base + 3], enc_max(m.w));
            if (lane == 0) atomicAdd(&g_cnt[cur], cnt);
            s = make_float4(0.f, 0.f, 0.f, 0.f);
            m = make_float4(-INFINITY, -INFINITY, -INFINITY, -INFINITY);
            cnt = 0;
            cur = b;
        }
        float4 v = ((const float4*)(g_agg + (size_t)node * FDIM))[lane];
        s.x += v.x; s.y += v.y; s.z += v.z; s.w += v.w;
        m.x = fmaxf(m.x, v.x); m.y = fmaxf(m.y, v.y);
        m.z = fmaxf(m.z, v.z); m.w = fmaxf(m.w, v.w);
        cnt++;
    }
    int base = cur * FDIM + lane * 4;
    atomicAdd(&g_sums[base + 0], s.x); atomicAdd(&g_sums[base + 1], s.y);
    atomicAdd(&g_sums[base + 2], s.z); atomicAdd(&g_sums[base + 3], s.w);
    atomicMax(&g_maxenc[base + 0], enc_max(m.x));
    atomicMax(&g_maxenc[base + 1], enc_max(m.y));
    atomicMax(&g_maxenc[base + 2], enc_max(m.z));
    atomicMax(&g_maxenc[base + 3], enc_max(m.w));
    if (lane == 0) atomicAdd(&g_cnt[cur], cnt);
}

// ---------------- classifier head: one block per graph ----------------------
__global__ void classifier_kernel(const float* __restrict__ Wc1, const float* __restrict__ bc1,
                                  const float* __restrict__ Wc2, const float* __restrict__ bc2,
                                  float* __restrict__ out) {
    int g = blockIdx.x, t = threadIdx.x;  // 128 threads
    __shared__ float gv[256];
    __shared__ float hs[128];

    int cnt = g_cnt[g];
    float inv = 1.0f / (float)max(cnt, 1);
    gv[t] = g_sums[g * FDIM + t] * inv;
    unsigned e = g_maxenc[g * FDIM + t];
    gv[128 + t] = (cnt == 0) ? 0.0f : dec_max(e);
    __syncthreads();

    float acc = bc1[t];
#pragma unroll 8
    for (int k = 0; k < 256; k++) acc += gv[k] * Wc1[k * 128 + t];
    hs[t] = fmaxf(acc, 0.0f);
    __syncthreads();

    if (t < 10) {
        float o = bc2[t];
#pragma unroll 8
        for (int k = 0; k < 128; k++) o += hs[k] * Wc2[k * 10 + t];
        out[g * 10 + t] = o;
    }
}

// ---------------- launch -----------------------------------------------------
extern "C" void kernel_launch(void* const* d_in, const int* in_sizes, int n_in,
                              void* d_out, int out_size) {
    const float* x     = (const float*)d_in[0];
    const int*   ei    = (const int*)d_in[1];
    const int*   src   = ei;
    const int*   dst   = ei + N_EDGES;
    const int*   batch = (const int*)d_in[2];
    const float* W1 = (const float*)d_in[3];  const float* b1 = (const float*)d_in[4];
    const float* W2 = (const float*)d_in[5];  const float* b2 = (const float*)d_in[6];
    const float* W3 = (const float*)d_in[7];  const float* b3 = (const float*)d_in[8];
    const float* Wc1 = (const float*)d_in[9]; const float* bc1 = (const float*)d_in[10];
    const float* Wc2 = (const float*)d_in[11]; const float* bc2 = (const float*)d_in[12];
    float* out = (float*)d_out;

    // preprocessing: degrees, CSR-by-dst with packed (src, norm) edges
    zero_kernel<<<(N_NODES + 255) / 256, 256>>>();
    hist_kernel<<<2048, 256>>>(dst);
    scan_part<<<SCAN_BLOCKS, 256>>>();
    scan_mid<<<1, 256>>>();
    scan_final<<<SCAN_BLOCKS, 256>>>();
    scatter_kernel<<<2048, 256>>>(src, dst);

    float* d_h;  cudaGetSymbolAddress((void**)&d_h, g_h);
    float* d_a;  cudaGetSymbolAddress((void**)&d_a, g_agg);

    const int GEMM_BLOCKS = (N_NODES + 63) / 64;            // 1563
    const int AGG_BLOCKS  = (N_NODES * 32 + 255) / 256;     // 12500

    gemm128<false><<<GEMM_BLOCKS, 256>>>(x, W1, d_h);
    agg_kernel<<<AGG_BLOCKS, 256>>>(d_h, b1, d_a);
    gemm128<true><<<GEMM_BLOCKS, 256>>>(d_a, W2, d_h);
    agg_kernel<<<AGG_BLOCKS, 256>>>(d_h, b2, d_a);
    gemm128<true><<<GEMM_BLOCKS, 256>>>(d_a, W3, d_h);
    agg_kernel<<<AGG_BLOCKS, 256>>>(d_h, b3, d_a);

    int pool_warps = (N_NODES + 31) / 32;
    pool_kernel<<<(pool_warps * 32 + 255) / 256, 256>>>(batch);
    classifier_kernel<<<N_GRAPHS, 128>>>(Wc1, bc1, Wc2, bc2, out);
}

// round 3
// speedup vs baseline: 1.3590x; 1.3590x over previous
#include <cuda_runtime.h>
#include <cstdint>

#define N_NODES 100000
#define N_EDGES 1600000
#define N_GRAPHS 512
#define FDIM 128
#define SCAN_CHUNK 512
#define SCAN_BLOCKS ((N_NODES + SCAN_CHUNK - 1) / SCAN_CHUNK)   // 196

// ---------------- device scratch (allocation-free: __device__ globals) ------
__device__ float    g_h[(size_t)N_NODES * FDIM];
__device__ float    g_agg[(size_t)N_NODES * FDIM];
__device__ int      g_deg[N_NODES];
__device__ int      g_cursor[N_NODES];
__device__ float    g_dinv[N_NODES];
__device__ int      g_rowoff[N_NODES + 1];
__device__ unsigned long long g_edge[N_EDGES];   // (norm<<32)|src
__device__ int      g_part[SCAN_BLOCKS];
__device__ float    g_sums[N_GRAPHS * FDIM];
__device__ unsigned g_maxenc[N_GRAPHS * FDIM];
__device__ int      g_cnt[N_GRAPHS];

// ---------------- helpers ---------------------------------------------------
__device__ __forceinline__ unsigned enc_max(float f) {
    unsigned u = __float_as_uint(f);
    return (u & 0x80000000u) ? ~u : (u | 0x80000000u);
}
__device__ __forceinline__ float dec_max(unsigned e) {
    unsigned bits = (e & 0x80000000u) ? (e ^ 0x80000000u) : ~e;
    return __uint_as_float(bits);
}

// ---------------- preprocessing ---------------------------------------------
__global__ void zero_kernel() {
    int i = blockIdx.x * blockDim.x + threadIdx.x;
    if (i < N_GRAPHS * FDIM) { g_sums[i] = 0.0f; g_maxenc[i] = 0u; }
    if (i < N_GRAPHS) g_cnt[i] = 0;
    if (i < N_NODES) g_deg[i] = 0;
}

__global__ void hist_kernel(const int* __restrict__ dst) {
    int stride = gridDim.x * blockDim.x;
    for (int e = blockIdx.x * blockDim.x + threadIdx.x; e < N_EDGES; e += stride)
        atomicAdd(&g_deg[dst[e]], 1);
}

// phase 1: per-block partial sums (256 thr, 512 elems/block)
__global__ void scan_part() {
    int b = blockIdx.x, t = threadIdx.x;
    int base = b * SCAN_CHUNK;
    int s = 0;
    for (int i = t; i < SCAN_CHUNK; i += 256) {
        int idx = base + i;
        if (idx < N_NODES) s += g_deg[idx];
    }
    __shared__ int sh[8];
#pragma unroll
    for (int o = 16; o; o >>= 1) s += __shfl_down_sync(~0u, s, o);
    if ((t & 31) == 0) sh[t >> 5] = s;
    __syncthreads();
    if (t < 8) {
        int v = sh[t];
#pragma unroll
        for (int o = 4; o; o >>= 1) v += __shfl_down_sync(0xffu, v, o);
        if (t == 0) g_part[b] = v;
    }
}

// phase 2: 1-block exclusive scan of 196 partials
__global__ void scan_mid() {
    __shared__ int sh[256];
    int t = threadIdx.x;
    int v = (t < SCAN_BLOCKS) ? g_part[t] : 0;
    sh[t] = v;
    __syncthreads();
    for (int o = 1; o < 256; o <<= 1) {
        int u = (t >= o) ? sh[t - o] : 0;
        __syncthreads();
        sh[t] += u;
        __syncthreads();
    }
    if (t < SCAN_BLOCKS) g_part[t] = sh[t] - v;   // exclusive
    if (t == 0) g_rowoff[N_NODES] = N_EDGES;      // total degree is always E
}

// phase 3: per-block rescan + dinv + cursor reset (2 elems/thread)
__global__ void scan_final() {
    int b = blockIdx.x, t = threadIdx.x;
    int base = b * SCAN_CHUNK;
    int i0 = base + 2 * t, i1 = i0 + 1;
    int d0 = (i0 < N_NODES) ? g_deg[i0] : 0;
    int d1 = (i1 < N_NODES) ? g_deg[i1] : 0;
    int s = d0 + d1;
    __shared__ int sh[256];
    sh[t] = s;
    __syncthreads();
    for (int o = 1; o < 256; o <<= 1) {
        int u = (t >= o) ? sh[t - o] : 0;
        __syncthreads();
        sh[t] += u;
        __syncthreads();
    }
    int excl = sh[t] - s + g_part[b];
    if (i0 < N_NODES) {
        g_rowoff[i0] = excl;
        g_dinv[i0] = rsqrtf((float)d0 + 1.0f);
        g_cursor[i0] = 0;
    }
    if (i1 < N_NODES) {
        g_rowoff[i1] = excl + d0;
        g_dinv[i1] = rsqrtf((float)d1 + 1.0f);
        g_cursor[i1] = 0;
    }
}

__global__ void scatter_kernel(const int* __restrict__ src, const int* __restrict__ dst) {
    int stride = gridDim.x * blockDim.x;
    for (int e = blockIdx.x * blockDim.x + threadIdx.x; e < N_EDGES; e += stride) {
        int s = src[e], d = dst[e];
        int pos = g_rowoff[d] + atomicAdd(&g_cursor[d], 1);
        float norm = g_dinv[s] * g_dinv[d];
        g_edge[pos] = (unsigned long long)(unsigned)s |
                      ((unsigned long long)__float_as_uint(norm) << 32);
    }
}

// ---------------- dense GEMM: out[N,128] = act(A[N,128]) @ W[128,128] -------
// (round-1 proven version: 32-row tiles, 256 threads, scalar FFMA)
template <bool RELU_IN>
__global__ void gemm128(const float* __restrict__ A, const float* __restrict__ W,
                        float* __restrict__ out) {
    __shared__ float As[32 * 128];
    __shared__ float Ws[32 * 128];
    int tid = threadIdx.x;            // 256 threads
    int row0 = blockIdx.x * 32;

    const float4* A4 = (const float4*)(A + (size_t)row0 * FDIM);
    float4* As4 = (float4*)As;
#pragma unroll
    for (int i = 0; i < 4; i++) {
        float4 v = A4[tid + i * 256];
        if (RELU_IN) {
            v.x = fmaxf(v.x, 0.0f); v.y = fmaxf(v.y, 0.0f);
            v.z = fmaxf(v.z, 0.0f); v.w = fmaxf(v.w, 0.0f);
        }
        As4[tid + i * 256] = v;
    }

    int warp = tid >> 5, lane = tid & 31;
    float4 acc[4];
#pragma unroll
    for (int r = 0; r < 4; r++) acc[r] = make_float4(0.f, 0.f, 0.f, 0.f);

    for (int kb = 0; kb < 4; kb++) {
        __syncthreads();
        const float4* W4 = (const float4*)(W + (size_t)kb * 32 * FDIM);
        float4* Ws4 = (float4*)Ws;
#pragma unroll
        for (int i = 0; i < 4; i++) Ws4[tid + i * 256] = W4[tid + i * 256];
        __syncthreads();
#pragma unroll
        for (int k = 0; k < 32; k++) {
            float4 w = ((const float4*)Ws)[k * 32 + lane];
#pragma unroll
            for (int r = 0; r < 4; r++) {
                float a = As[(warp * 4 + r) * FDIM + kb * 32 + k];
                acc[r].x += a * w.x; acc[r].y += a * w.y;
                acc[r].z += a * w.z; acc[r].w += a * w.w;
            }
        }
    }
#pragma unroll
    for (int r = 0; r < 4; r++) {
        int row = row0 + warp * 4 + r;
        ((float4*)(out + (size_t)row * FDIM))[lane] = acc[r];
    }
}

// ---------------- aggregation: one warp per dst node (no atomics) -----------
__global__ void agg_kernel(const float* __restrict__ h, const float* __restrict__ bias,
                           float* __restrict__ out) {
    int warpid = (blockIdx.x * blockDim.x + threadIdx.x) >> 5;
    int lane = threadIdx.x & 31;
    if (warpid >= N_NODES) return;
    int node = warpid;

    float di = g_dinv[node];
    float sc = di * di;
    float4 b4 = ((const float4*)bias)[lane];
    float4 hv = ((const float4*)(h + (size_t)node * FDIM))[lane];
    float4 acc;
    acc.x = b4.x + hv.x * sc; acc.y = b4.y + hv.y * sc;
    acc.z = b4.z + hv.z * sc; acc.w = b4.w + hv.w * sc;

    int beg = g_rowoff[node], end = g_rowoff[node + 1];
    for (int i = beg; i < end; i++) {
        unsigned long long e = __ldg(&g_edge[i]);
        int s = (int)(unsigned)e;
        float w = __uint_as_float((unsigned)(e >> 32));
        float4 v = __ldg((const float4*)(h + (size_t)s * FDIM) + lane);
        acc.x += w * v.x; acc.y += w * v.y; acc.z += w * v.z; acc.w += w * v.w;
    }
    ((float4*)(out + (size_t)node * FDIM))[lane] = acc;
}

// ---------------- pooling: warp handles 32 consecutive nodes (sorted batch) -
__global__ void pool_kernel(const int* __restrict__ batch) {
    int warpid = (blockIdx.x * blockDim.x + threadIdx.x) >> 5;
    int lane = threadIdx.x & 31;
    int beg = warpid * 32;
    if (beg >= N_NODES) return;
    int end = min(beg + 32, N_NODES);

    int cur = batch[beg];
    float4 s = make_float4(0.f, 0.f, 0.f, 0.f);
    float4 m = make_float4(-INFINITY, -INFINITY, -INFINITY, -INFINITY);
    int cnt = 0;

    for (int node = beg; node < end; node++) {
        int b = batch[node];
        if (b != cur) {
            int base = cur * FDIM + lane * 4;
            atomicAdd(&g_sums[base + 0], s.x); atomicAdd(&g_sums[base + 1], s.y);
            atomicAdd(&g_sums[base + 2], s.z); atomicAdd(&g_sums[base + 3], s.w);
            atomicMax(&g_maxenc[base + 0], enc_max(m.x));
            atomicMax(&g_maxenc[base + 1], enc_max(m.y));
            atomicMax(&g_maxenc[base + 2], enc_max(m.z));
            atomicMax(&g_maxenc[base + 3], enc_max(m.w));
            if (lane == 0) atomicAdd(&g_cnt[cur], cnt);
            s = make_float4(0.f, 0.f, 0.f, 0.f);
            m = make_float4(-INFINITY, -INFINITY, -INFINITY, -INFINITY);
            cnt = 0;
            cur = b;
        }
        float4 v = ((const float4*)(g_agg + (size_t)node * FDIM))[lane];
        s.x += v.x; s.y += v.y; s.z += v.z; s.w += v.w;
        m.x = fmaxf(m.x, v.x); m.y = fmaxf(m.y, v.y);
        m.z = fmaxf(m.z, v.z); m.w = fmaxf(m.w, v.w);
        cnt++;
    }
    int base = cur * FDIM + lane * 4;
    atomicAdd(&g_sums[base + 0], s.x); atomicAdd(&g_sums[base + 1], s.y);
    atomicAdd(&g_sums[base + 2], s.z); atomicAdd(&g_sums[base + 3], s.w);
    atomicMax(&g_maxenc[base + 0], enc_max(m.x));
    atomicMax(&g_maxenc[base + 1], enc_max(m.y));
    atomicMax(&g_maxenc[base + 2], enc_max(m.z));
    atomicMax(&g_maxenc[base + 3], enc_max(m.w));
    if (lane == 0) atomicAdd(&g_cnt[cur], cnt);
}

// ---------------- classifier head: one block per graph ----------------------
__global__ void classifier_kernel(const float* __restrict__ Wc1, const float* __restrict__ bc1,
                                  const float* __restrict__ Wc2, const float* __restrict__ bc2,
                                  float* __restrict__ out) {
    int g = blockIdx.x, t = threadIdx.x;  // 128 threads
    __shared__ float gv[256];
    __shared__ float hs[128];

    int cnt = g_cnt[g];
    float inv = 1.0f / (float)max(cnt, 1);
    gv[t] = g_sums[g * FDIM + t] * inv;
    unsigned e = g_maxenc[g * FDIM + t];
    gv[128 + t] = (cnt == 0) ? 0.0f : dec_max(e);
    __syncthreads();

    float acc = bc1[t];
#pragma unroll 8
    for (int k = 0; k < 256; k++) acc += gv[k] * Wc1[k * 128 + t];
    hs[t] = fmaxf(acc, 0.0f);
    __syncthreads();

    if (t < 10) {
        float o = bc2[t];
#pragma unroll 8
        for (int k = 0; k < 128; k++) o += hs[k] * Wc2[k * 10 + t];
        out[g * 10 + t] = o;
    }
}

// ---------------- launch -----------------------------------------------------
extern "C" void kernel_launch(void* const* d_in, const int* in_sizes, int n_in,
                              void* d_out, int out_size) {
    const float* x     = (const float*)d_in[0];
    const int*   ei    = (const int*)d_in[1];
    const int*   src   = ei;
    const int*   dst   = ei + N_EDGES;
    const int*   batch = (const int*)d_in[2];
    const float* W1 = (const float*)d_in[3];  const float* b1 = (const float*)d_in[4];
    const float* W2 = (const float*)d_in[5];  const float* b2 = (const float*)d_in[6];
    const float* W3 = (const float*)d_in[7];  const float* b3 = (const float*)d_in[8];
    const float* Wc1 = (const float*)d_in[9]; const float* bc1 = (const float*)d_in[10];
    const float* Wc2 = (const float*)d_in[11]; const float* bc2 = (const float*)d_in[12];
    float* out = (float*)d_out;

    // preprocessing: degrees, CSR-by-dst with packed (src, norm) edges
    zero_kernel<<<(N_NODES + 255) / 256, 256>>>();
    hist_kernel<<<2048, 256>>>(dst);
    scan_part<<<SCAN_BLOCKS, 256>>>();
    scan_mid<<<1, 256>>>();
    scan_final<<<SCAN_BLOCKS, 256>>>();
    scatter_kernel<<<2048, 256>>>(src, dst);

    float* d_h;  cudaGetSymbolAddress((void**)&d_h, g_h);
    float* d_a;  cudaGetSymbolAddress((void**)&d_a, g_agg);

    const int GEMM_BLOCKS = N_NODES / 32;                   // 3125
    const int AGG_BLOCKS  = (N_NODES * 32 + 255) / 256;     // 12500

    gemm128<false><<<GEMM_BLOCKS, 256>>>(x, W1, d_h);
    agg_kernel<<<AGG_BLOCKS, 256>>>(d_h, b1, d_a);
    gemm128<true><<<GEMM_BLOCKS, 256>>>(d_a, W2, d_h);
    agg_kernel<<<AGG_BLOCKS, 256>>>(d_h, b2, d_a);
    gemm128<true><<<GEMM_BLOCKS, 256>>>(d_a, W3, d_h);
    agg_kernel<<<AGG_BLOCKS, 256>>>(d_h, b3, d_a);

    int pool_warps = (N_NODES + 31) / 32;
    pool_kernel<<<(pool_warps * 32 + 255) / 256, 256>>>(batch);
    classifier_kernel<<<N_GRAPHS, 128>>>(Wc1, bc1, Wc2, bc2, out);
}

// round 6
// speedup vs baseline: 1.4550x; 1.0706x over previous
#include <cuda_runtime.h>
#include <cstdint>

#define N_NODES 100000
#define N_EDGES 1600000
#define N_GRAPHS 512
#define FDIM 128
#define SCAN_CHUNK 512
#define SCAN_BLOCKS ((N_NODES + SCAN_CHUNK - 1) / SCAN_CHUNK)   // 196

// ---------------- device scratch (allocation-free: __device__ globals) ------
__device__ float    g_h[(size_t)N_NODES * FDIM];
__device__ float    g_agg[(size_t)N_NODES * FDIM];
__device__ int      g_deg[N_NODES];
__device__ int      g_cursor[N_NODES];
__device__ float    g_dinv[N_NODES];
__device__ int      g_rowoff[N_NODES + 1];
__device__ unsigned long long g_edge[N_EDGES];   // (norm<<32)|src
__device__ int      g_part[SCAN_BLOCKS];
__device__ float    g_sums[N_GRAPHS * FDIM];
__device__ unsigned g_maxenc[N_GRAPHS * FDIM];
__device__ int      g_cnt[N_GRAPHS];

// ---------------- helpers ---------------------------------------------------
__device__ __forceinline__ unsigned enc_max(float f) {
    unsigned u = __float_as_uint(f);
    return (u & 0x80000000u) ? ~u : (u | 0x80000000u);
}
__device__ __forceinline__ float dec_max(unsigned e) {
    unsigned bits = (e & 0x80000000u) ? (e ^ 0x80000000u) : ~e;
    return __uint_as_float(bits);
}

// ---------------- preprocessing ---------------------------------------------
__global__ void zero_kernel() {
    int i = blockIdx.x * blockDim.x + threadIdx.x;
    if (i < N_GRAPHS * FDIM) { g_sums[i] = 0.0f; g_maxenc[i] = 0u; }
    if (i < N_GRAPHS) g_cnt[i] = 0;
    if (i < N_NODES) g_deg[i] = 0;
}

__global__ void hist_kernel(const int* __restrict__ dst) {
    int stride = gridDim.x * blockDim.x;
    for (int e = blockIdx.x * blockDim.x + threadIdx.x; e < N_EDGES; e += stride)
        atomicAdd(&g_deg[dst[e]], 1);
}

__global__ void scan_part() {
    int b = blockIdx.x, t = threadIdx.x;
    int base = b * SCAN_CHUNK;
    int s = 0;
    for (int i = t; i < SCAN_CHUNK; i += 256) {
        int idx = base + i;
        if (idx < N_NODES) s += g_deg[idx];
    }
    __shared__ int sh[8];
#pragma unroll
    for (int o = 16; o; o >>= 1) s += __shfl_down_sync(~0u, s, o);
    if ((t & 31) == 0) sh[t >> 5] = s;
    __syncthreads();
    if (t < 8) {
        int v = sh[t];
#pragma unroll
        for (int o = 4; o; o >>= 1) v += __shfl_down_sync(0xffu, v, o);
        if (t == 0) g_part[b] = v;
    }
}

__global__ void scan_mid() {
    __shared__ int sh[256];
    int t = threadIdx.x;
    int v = (t < SCAN_BLOCKS) ? g_part[t] : 0;
    sh[t] = v;
    __syncthreads();
    for (int o = 1; o < 256; o <<= 1) {
        int u = (t >= o) ? sh[t - o] : 0;
        __syncthreads();
        sh[t] += u;
        __syncthreads();
    }
    if (t < SCAN_BLOCKS) g_part[t] = sh[t] - v;
    if (t == 0) g_rowoff[N_NODES] = N_EDGES;
}

__global__ void scan_final() {
    int b = blockIdx.x, t = threadIdx.x;
    int base = b * SCAN_CHUNK;
    int i0 = base + 2 * t, i1 = i0 + 1;
    int d0 = (i0 < N_NODES) ? g_deg[i0] : 0;
    int d1 = (i1 < N_NODES) ? g_deg[i1] : 0;
    int s = d0 + d1;
    __shared__ int sh[256];
    sh[t] = s;
    __syncthreads();
    for (int o = 1; o < 256; o <<= 1) {
        int u = (t >= o) ? sh[t - o] : 0;
        __syncthreads();
        sh[t] += u;
        __syncthreads();
    }
    int excl = sh[t] - s + g_part[b];
    if (i0 < N_NODES) {
        g_rowoff[i0] = excl;
        g_dinv[i0] = rsqrtf((float)d0 + 1.0f);
        g_cursor[i0] = 0;
    }
    if (i1 < N_NODES) {
        g_rowoff[i1] = excl + d0;
        g_dinv[i1] = rsqrtf((float)d1 + 1.0f);
        g_cursor[i1] = 0;
    }
}

__global__ void scatter_kernel(const int* __restrict__ src, const int* __restrict__ dst) {
    int stride = gridDim.x * blockDim.x;
    for (int e = blockIdx.x * blockDim.x + threadIdx.x; e < N_EDGES; e += stride) {
        int s = src[e], d = dst[e];
        int pos = g_rowoff[d] + atomicAdd(&g_cursor[d], 1);
        float norm = g_dinv[s] * g_dinv[d];
        g_edge[pos] = (unsigned long long)(unsigned)s |
                      ((unsigned long long)__float_as_uint(norm) << 32);
    }
}

// ---------------- dense GEMM: out[N,128] = act(A[N,128]) @ W[128,128] -------
// (proven: 32-row tiles, 256 threads, scalar FFMA — at the fp32 issue roofline)
template <bool RELU_IN>
__global__ void gemm128(const float* __restrict__ A, const float* __restrict__ W,
                        float* __restrict__ out) {
    __shared__ float As[32 * 128];
    __shared__ float Ws[32 * 128];
    int tid = threadIdx.x;            // 256 threads
    int row0 = blockIdx.x * 32;

    const float4* A4 = (const float4*)(A + (size_t)row0 * FDIM);
    float4* As4 = (float4*)As;
#pragma unroll
    for (int i = 0; i < 4; i++) {
        float4 v = A4[tid + i * 256];
        if (RELU_IN) {
            v.x = fmaxf(v.x, 0.0f); v.y = fmaxf(v.y, 0.0f);
            v.z = fmaxf(v.z, 0.0f); v.w = fmaxf(v.w, 0.0f);
        }
        As4[tid + i * 256] = v;
    }

    int warp = tid >> 5, lane = tid & 31;
    float4 acc[4];
#pragma unroll
    for (int r = 0; r < 4; r++) acc[r] = make_float4(0.f, 0.f, 0.f, 0.f);

    for (int kb = 0; kb < 4; kb++) {
        __syncthreads();
        const float4* W4 = (const float4*)(W + (size_t)kb * 32 * FDIM);
        float4* Ws4 = (float4*)Ws;
#pragma unroll
        for (int i = 0; i < 4; i++) Ws4[tid + i * 256] = W4[tid + i * 256];
        __syncthreads();
#pragma unroll
        for (int k = 0; k < 32; k++) {
            float4 w = ((const float4*)Ws)[k * 32 + lane];
#pragma unroll
            for (int r = 0; r < 4; r++) {
                float a = As[(warp * 4 + r) * FDIM + kb * 32 + k];
                acc[r].x += a * w.x; acc[r].y += a * w.y;
                acc[r].z += a * w.z; acc[r].w += a * w.w;
            }
        }
    }
#pragma unroll
    for (int r = 0; r < 4; r++) {
        int row = row0 + warp * 4 + r;
        ((float4*)(out + (size_t)row * FDIM))[lane] = acc[r];
    }
}

// ---------------- aggregation: warp per dst node, batched edge loads --------
__global__ void agg_kernel(const float* __restrict__ h, const float* __restrict__ bias,
                           float* __restrict__ out) {
    int warpid = (blockIdx.x * blockDim.x + threadIdx.x) >> 5;
    int lane = threadIdx.x & 31;
    if (warpid >= N_NODES) return;
    int node = warpid;

    float di = g_dinv[node];
    float sc = di * di;
    float4 b4 = ((const float4*)bias)[lane];
    float4 hv = ((const float4*)(h + (size_t)node * FDIM))[lane];
    float4 acc;
    acc.x = b4.x + hv.x * sc; acc.y = b4.y + hv.y * sc;
    acc.z = b4.z + hv.z * sc; acc.w = b4.w + hv.w * sc;

    int beg = g_rowoff[node];
    int deg = g_rowoff[node + 1] - beg;

    for (int base = 0; base < deg; base += 32) {
        int n = deg - base; if (n > 32) n = 32;
        // coalesced: lane j holds edge (base+j); distribute via shfl
        unsigned lo = 0, hi = 0;
        if (base + lane < deg) {
            unsigned long long e = __ldg(&g_edge[beg + base + lane]);
            lo = (unsigned)e;
            hi = (unsigned)(e >> 32);
        }
#pragma unroll 4
        for (int j = 0; j < n; j++) {
            int s = (int)__shfl_sync(~0u, lo, j);
            float w = __uint_as_float(__shfl_sync(~0u, hi, j));
            float4 v = __ldg((const float4*)(h + (size_t)s * FDIM) + lane);
            acc.x += w * v.x; acc.y += w * v.y;
            acc.z += w * v.z; acc.w += w * v.w;
        }
    }
    ((float4*)(out + (size_t)node * FDIM))[lane] = acc;
}

// ---------------- pooling: warp handles 32 consecutive nodes (sorted batch) -
__global__ void pool_kernel(const int* __restrict__ batch) {
    int warpid = (blockIdx.x * blockDim.x + threadIdx.x) >> 5;
    int lane = threadIdx.x & 31;
    int beg = warpid * 32;
    if (beg >= N_NODES) return;
    int end = min(beg + 32, N_NODES);

    int cur = batch[beg];
    float4 s = make_float4(0.f, 0.f, 0.f, 0.f);
    float4 m = make_float4(-INFINITY, -INFINITY, -INFINITY, -INFINITY);
    int cnt = 0;

    for (int node = beg; node < end; node++) {
        int b = batch[node];
        if (b != cur) {
            int base = cur * FDIM + lane * 4;
            atomicAdd(&g_sums[base + 0], s.x); atomicAdd(&g_sums[base + 1], s.y);
            atomicAdd(&g_sums[base + 2], s.z); atomicAdd(&g_sums[base + 3], s.w);
            atomicMax(&g_maxenc[base + 0], enc_max(m.x));
            atomicMax(&g_maxenc[base + 1], enc_max(m.y));
            atomicMax(&g_maxenc[base + 2], enc_max(m.z));
            atomicMax(&g_maxenc[base + 3], enc_max(m.w));
            if (lane == 0) atomicAdd(&g_cnt[cur], cnt);
            s = make_float4(0.f, 0.f, 0.f, 0.f);
            m = make_float4(-INFINITY, -INFINITY, -INFINITY, -INFINITY);
            cnt = 0;
            cur = b;
        }
        float4 v = ((const float4*)(g_agg + (size_t)node * FDIM))[lane];
        s.x += v.x; s.y += v.y; s.z += v.z; s.w += v.w;
        m.x = fmaxf(m.x, v.x); m.y = fmaxf(m.y, v.y);
        m.z = fmaxf(m.z, v.z); m.w = fmaxf(m.w, v.w);
        cnt++;
    }
    int base = cur * FDIM + lane * 4;
    atomicAdd(&g_sums[base + 0], s.x); atomicAdd(&g_sums[base + 1], s.y);
    atomicAdd(&g_sums[base + 2], s.z); atomicAdd(&g_sums[base + 3], s.w);
    atomicMax(&g_maxenc[base + 0], enc_max(m.x));
    atomicMax(&g_maxenc[base + 1], enc_max(m.y));
    atomicMax(&g_maxenc[base + 2], enc_max(m.z));
    atomicMax(&g_maxenc[base + 3], enc_max(m.w));
    if (lane == 0) atomicAdd(&g_cnt[cur], cnt);
}

// ---------------- classifier head: one block per graph ----------------------
__global__ void classifier_kernel(const float* __restrict__ Wc1, const float* __restrict__ bc1,
                                  const float* __restrict__ Wc2, const float* __restrict__ bc2,
                                  float* __restrict__ out) {
    int g = blockIdx.x, t = threadIdx.x;  // 128 threads
    __shared__ float gv[256];
    __shared__ float hs[128];

    int cnt = g_cnt[g];
    float inv = 1.0f / (float)max(cnt, 1);
    gv[t] = g_sums[g * FDIM + t] * inv;
    unsigned e = g_maxenc[g * FDIM + t];
    gv[128 + t] = (cnt == 0) ? 0.0f : dec_max(e);
    __syncthreads();

    float acc = bc1[t];
#pragma unroll 8
    for (int k = 0; k < 256; k++) acc += gv[k] * Wc1[k * 128 + t];
    hs[t] = fmaxf(acc, 0.0f);
    __syncthreads();

    if (t < 10) {
        float o = bc2[t];
#pragma unroll 8
        for (int k = 0; k < 128; k++) o += hs[k] * Wc2[k * 10 + t];
        out[g * 10 + t] = o;
    }
}

// ---------------- launch -----------------------------------------------------
extern "C" void kernel_launch(void* const* d_in, const int* in_sizes, int n_in,
                              void* d_out, int out_size) {
    const float* x     = (const float*)d_in[0];
    const int*   ei    = (const int*)d_in[1];
    const int*   src   = ei;
    const int*   dst   = ei + N_EDGES;
    const int*   batch = (const int*)d_in[2];
    const float* W1 = (const float*)d_in[3];  const float* b1 = (const float*)d_in[4];
    const float* W2 = (const float*)d_in[5];  const float* b2 = (const float*)d_in[6];
    const float* W3 = (const float*)d_in[7];  const float* b3 = (const float*)d_in[8];
    const float* Wc1 = (const float*)d_in[9]; const float* bc1 = (const float*)d_in[10];
    const float* Wc2 = (const float*)d_in[11]; const float* bc2 = (const float*)d_in[12];
    float* out = (float*)d_out;

    // side stream + events, created once on the (uncaptured) correctness call
    static cudaStream_t s2 = nullptr;
    static cudaEvent_t ev_fork = nullptr, ev_join = nullptr;
    if (s2 == nullptr) {
        cudaStreamCreateWithFlags(&s2, cudaStreamNonBlocking);
        cudaEventCreateWithFlags(&ev_fork, cudaEventDisableTiming);
        cudaEventCreateWithFlags(&ev_join, cudaEventDisableTiming);
    }

    float* d_h;  cudaGetSymbolAddress((void**)&d_h, g_h);
    float* d_a;  cudaGetSymbolAddress((void**)&d_a, g_agg);

    const int GEMM_BLOCKS = N_NODES / 32;                   // 3125
    const int AGG_BLOCKS  = (N_NODES * 32 + 255) / 256;     // 12500

    // fork: preprocessing on s2 runs concurrently with GEMM1 on the main stream
    cudaEventRecord(ev_fork, 0);
    cudaStreamWaitEvent(s2, ev_fork, 0);

    zero_kernel<<<(N_NODES + 255) / 256, 256, 0, s2>>>();
    hist_kernel<<<2048, 256, 0, s2>>>(dst);
    scan_part<<<SCAN_BLOCKS, 256, 0, s2>>>();
    scan_mid<<<1, 256, 0, s2>>>();
    scan_final<<<SCAN_BLOCKS, 256, 0, s2>>>();
    scatter_kernel<<<2048, 256, 0, s2>>>(src, dst);
    cudaEventRecord(ev_join, s2);

    gemm128<false><<<GEMM_BLOCKS, 256>>>(x, W1, d_h);

    // join: agg1 needs both GEMM1 and the CSR build
    cudaStreamWaitEvent(0, ev_join, 0);

    agg_kernel<<<AGG_BLOCKS, 256>>>(d_h, b1, d_a);
    gemm128<true><<<GEMM_BLOCKS, 256>>>(d_a, W2, d_h);
    agg_kernel<<<AGG_BLOCKS, 256>>>(d_h, b2, d_a);
    gemm128<true><<<GEMM_BLOCKS, 256>>>(d_a, W3, d_h);
    agg_kernel<<<AGG_BLOCKS, 256>>>(d_h, b3, d_a);

    int pool_warps = (N_NODES + 31) / 32;
    pool_kernel<<<(pool_warps * 32 + 255) / 256, 256>>>(batch);
    classifier_kernel<<<N_GRAPHS, 128>>>(Wc1, bc1, Wc2, bc2, out);
}